// round 1
// baseline (speedup 1.0000x reference)
#include <cuda_runtime.h>
#include <math.h>

// Clockwork RNN, hierarchically decomposed.
// B=128, T=512, I=2, H=1024, NM=8, MS=128.
//
// Module m (rows [m*128,(m+1)*128)) reads only modules >= m and updates at
// t % 2^m == 0. We compute trajectories top-down (m=7..0):
//   - chain<m>: K_m = 512>>m sequential steps of the 128x128 diagonal block
//     (batch-parallel: one CTA per batch element, weights in registers).
//   - g_kernel(m): GEMM of module m's full trajectory against
//     W_hh[0:m*128, m-block]^T -> precomputed context for all lower modules.
// Final fc output = per-state partials (pout) + gather assembly.

#define NB   128
#define NT   512
#define NH   1024
#define NMOD 8
#define MSZ  128

// States per module: K_m + 1 (index 0 = h0 from encoder, k+1 = update k)
__constant__ int c_TOFF[8] = {0, 513, 770, 899, 964, 997, 1014, 1023}; // prefix of S
__constant__ long long c_GOFF[8] = {0, 0, 4210688, 8437760, 11632640,
                                    13795328, 15187968, 16072704};

// Static scratch (allocation-free rule): trajectories, context GEMMs, fc partials
__device__ float g_traj[16842752];         // 1028 states * 128 b * 128 -> 67.4 MB
__device__ float g_G[16646144];            // sum_m' S_m' * 128 * (m'*128) -> 66.6 MB
__device__ float g_pout[1028 * NB * 2];

// ---------------------------------------------------------------------------
// h0 = x[:,0] @ enc_w.T  -> state 0 of every module trajectory
// ---------------------------------------------------------------------------
__global__ void h0_kernel(const float* __restrict__ x,
                          const float* __restrict__ enc_w) {
    const int b = blockIdx.x;
    const int m = blockIdx.y;
    const int r = threadIdx.x;
    const int h = m * MSZ + r;
    const float x0 = x[(size_t)b * (NT + 1) * 2 + 0];
    const float x1 = x[(size_t)b * (NT + 1) * 2 + 1];
    const float v = x0 * enc_w[h * 2 + 0] + x1 * enc_w[h * 2 + 1];
    g_traj[((size_t)c_TOFF[m] * NB + b) * MSZ + r] = v;
}

// ---------------------------------------------------------------------------
// Sequential diagonal chain for module M. One CTA per batch element.
// Thread r owns output unit r; its 128 diag weights live in registers.
// Context from higher modules comes from precomputed g_G (gather-sum).
// ---------------------------------------------------------------------------
template <int M>
__global__ __launch_bounds__(MSZ, 1) void chain_kernel(
    const float* __restrict__ x,
    const float* __restrict__ W_ih,
    const float* __restrict__ W_hh) {
    const int b = blockIdx.x;
    const int r = threadIdx.x;
    const int mbase = M * MSZ;
    __shared__ float h_s[MSZ];

    float Wreg[MSZ];
#pragma unroll
    for (int c = 0; c < MSZ; c++)
        Wreg[c] = W_hh[(size_t)(mbase + r) * NH + mbase + c];
    const float wih0 = W_ih[(mbase + r) * 2 + 0];
    const float wih1 = W_ih[(mbase + r) * 2 + 1];

    const size_t tbase = ((size_t)c_TOFF[M] * NB + b) * MSZ;
    h_s[r] = g_traj[tbase + r];
    __syncthreads();

    const int K = NT >> M;
    for (int k = 0; k < K; k++) {
        const int t = k << M;
        // external context: x term + precomputed higher-module contributions
        float gsum = x[((size_t)b * (NT + 1) + (t + 1)) * 2 + 0] * wih0 +
                     x[((size_t)b * (NT + 1) + (t + 1)) * 2 + 1] * wih1;
#pragma unroll
        for (int mp = M + 1; mp < NMOD; mp++) {
            const int s = (t == 0) ? 0 : (((t - 1) >> mp) + 1);
            gsum += g_G[c_GOFF[mp] + (size_t)(s * NB + b) * (mp * MSZ) +
                        mbase + r];
        }
        // diagonal block matvec (weights in regs, h broadcast from smem)
        float acc = 0.f;
        const float4* h4 = (const float4*)h_s;
#pragma unroll
        for (int c4 = 0; c4 < MSZ / 4; c4++) {
            const float4 hv = h4[c4];
            acc += Wreg[4 * c4 + 0] * hv.x;
            acc += Wreg[4 * c4 + 1] * hv.y;
            acc += Wreg[4 * c4 + 2] * hv.z;
            acc += Wreg[4 * c4 + 3] * hv.w;
        }
        const float hn = tanhf(acc + gsum);
        __syncthreads();
        h_s[r] = hn;
        g_traj[tbase + (size_t)(k + 1) * (NB * MSZ) + r] = hn;
        __syncthreads();
    }
}

// ---------------------------------------------------------------------------
// G_{mp} = Traj_{mp} (S*128 rows x 128) @ W_hh[0:mp*128, mp-block]^T
// Tiled 64x64 fp32 GEMM, K=128 in chunks of 32. All dims divide tiles exactly.
// ---------------------------------------------------------------------------
__global__ __launch_bounds__(256) void g_kernel(const float* __restrict__ W_hh,
                                                int mp) {
    __shared__ float As[64][33];
    __shared__ float Ws[64][33];
    const int N = mp * MSZ;
    const float* A = g_traj + (size_t)c_TOFF[mp] * (NB * MSZ);
    float* C = g_G + c_GOFF[mp];
    const int row0 = blockIdx.x * 64;
    const int n0 = blockIdx.y * 64;
    const int tid = threadIdx.x;
    const int tx = tid & 15;
    const int ty = tid >> 4;

    float acc[4][4] = {};
    for (int kk = 0; kk < MSZ; kk += 32) {
#pragma unroll
        for (int j = 0; j < 2; j++) {
            const int idx = tid + j * 256;  // float4 units, 0..511
            const int i = idx >> 3;
            const int c4 = idx & 7;
            float4 v = *(const float4*)(A + (size_t)(row0 + i) * MSZ + kk +
                                        c4 * 4);
            As[i][c4 * 4 + 0] = v.x; As[i][c4 * 4 + 1] = v.y;
            As[i][c4 * 4 + 2] = v.z; As[i][c4 * 4 + 3] = v.w;
            float4 w = *(const float4*)(W_hh + (size_t)(n0 + i) * NH +
                                        mp * MSZ + kk + c4 * 4);
            Ws[i][c4 * 4 + 0] = w.x; Ws[i][c4 * 4 + 1] = w.y;
            Ws[i][c4 * 4 + 2] = w.z; Ws[i][c4 * 4 + 3] = w.w;
        }
        __syncthreads();
#pragma unroll
        for (int c = 0; c < 32; c++) {
            float a[4], w[4];
#pragma unroll
            for (int i = 0; i < 4; i++) a[i] = As[ty * 4 + i][c];
#pragma unroll
            for (int j = 0; j < 4; j++) w[j] = Ws[tx * 4 + j][c];
#pragma unroll
            for (int i = 0; i < 4; i++)
#pragma unroll
                for (int j = 0; j < 4; j++) acc[i][j] += a[i] * w[j];
        }
        __syncthreads();
    }
#pragma unroll
    for (int i = 0; i < 4; i++)
#pragma unroll
        for (int j = 0; j < 4; j++)
            C[(size_t)(row0 + ty * 4 + i) * N + n0 + tx * 4 + j] = acc[i][j];
}

// ---------------------------------------------------------------------------
// fc partials per stored state: pout[gs,b,i] = Traj[gs,b,:] . fc_w[i, m-block]
// ---------------------------------------------------------------------------
__global__ __launch_bounds__(MSZ) void pout_kernel(
    const float* __restrict__ fc_w) {
    const int gs = blockIdx.x;
    const int b = blockIdx.y;
    const int r = threadIdx.x;
    int m = 0;
#pragma unroll
    for (int j = 1; j < 8; j++)
        if (gs >= c_TOFF[j]) m = j;
    const float v = g_traj[((size_t)gs * NB + b) * MSZ + r];
    const int col = m * MSZ + r;
    float a0 = v * fc_w[col];
    float a1 = v * fc_w[NH + col];
#pragma unroll
    for (int off = 16; off > 0; off >>= 1) {
        a0 += __shfl_down_sync(0xffffffffu, a0, off);
        a1 += __shfl_down_sync(0xffffffffu, a1, off);
    }
    __shared__ float s0[4], s1[4];
    if ((r & 31) == 0) { s0[r >> 5] = a0; s1[r >> 5] = a1; }
    __syncthreads();
    if (r == 0) {
        g_pout[((size_t)gs * NB + b) * 2 + 0] = s0[0] + s0[1] + s0[2] + s0[3];
        g_pout[((size_t)gs * NB + b) * 2 + 1] = s1[0] + s1[1] + s1[2] + s1[3];
    }
}

// ---------------------------------------------------------------------------
// out[b,t,i] = fc_b[i] + sum_m pout[state_of(m,t), b, i]
// ---------------------------------------------------------------------------
__global__ void assemble_kernel(const float* __restrict__ fc_b,
                                float* __restrict__ out) {
    const int idx = blockIdx.x * blockDim.x + threadIdx.x;  // b*512 + t
    const int b = idx >> 9;
    const int t = idx & 511;
    float o0 = fc_b[0];
    float o1 = fc_b[1];
#pragma unroll
    for (int m = 0; m < NMOD; m++) {
        const int gs = c_TOFF[m] + (t >> m) + 1;
        o0 += g_pout[((size_t)gs * NB + b) * 2 + 0];
        o1 += g_pout[((size_t)gs * NB + b) * 2 + 1];
    }
    out[(size_t)idx * 2 + 0] = o0;
    out[(size_t)idx * 2 + 1] = o1;
}

// ---------------------------------------------------------------------------
extern "C" void kernel_launch(void* const* d_in, const int* in_sizes, int n_in,
                              void* d_out, int out_size) {
    const float* x     = (const float*)d_in[0];  // [128, 513, 2, 1]
    const float* W_ih  = (const float*)d_in[1];  // [1024, 2]
    const float* W_hh  = (const float*)d_in[2];  // [1024, 1024]
    const float* fc_w  = (const float*)d_in[3];  // [2, 1024]
    const float* fc_b  = (const float*)d_in[4];  // [2]
    const float* enc_w = (const float*)d_in[5];  // [1024, 2]
    float* out = (float*)d_out;                  // [128, 512, 2]

    h0_kernel<<<dim3(NB, 8), MSZ>>>(x, enc_w);

    // top-down: chain m, then its contribution GEMM for all lower modules
    chain_kernel<7><<<NB, MSZ>>>(x, W_ih, W_hh);
    g_kernel<<<dim3(5 * 2, 7 * 2), 256>>>(W_hh, 7);
    chain_kernel<6><<<NB, MSZ>>>(x, W_ih, W_hh);
    g_kernel<<<dim3(9 * 2, 6 * 2), 256>>>(W_hh, 6);
    chain_kernel<5><<<NB, MSZ>>>(x, W_ih, W_hh);
    g_kernel<<<dim3(17 * 2, 5 * 2), 256>>>(W_hh, 5);
    chain_kernel<4><<<NB, MSZ>>>(x, W_ih, W_hh);
    g_kernel<<<dim3(33 * 2, 4 * 2), 256>>>(W_hh, 4);
    chain_kernel<3><<<NB, MSZ>>>(x, W_ih, W_hh);
    g_kernel<<<dim3(65 * 2, 3 * 2), 256>>>(W_hh, 3);
    chain_kernel<2><<<NB, MSZ>>>(x, W_ih, W_hh);
    g_kernel<<<dim3(129 * 2, 2 * 2), 256>>>(W_hh, 2);
    chain_kernel<1><<<NB, MSZ>>>(x, W_ih, W_hh);
    g_kernel<<<dim3(257 * 2, 1 * 2), 256>>>(W_hh, 1);
    chain_kernel<0><<<NB, MSZ>>>(x, W_ih, W_hh);

    pout_kernel<<<dim3(1028, NB), MSZ>>>(fc_w);
    assemble_kernel<<<(NB * NT) / 256, 256>>>(fc_b, out);
}

// round 2
// speedup vs baseline: 1.1612x; 1.1612x over previous
#include <cuda_runtime.h>
#include <math.h>

// Clockwork RNN, hierarchically decomposed (see round-1 notes).
// B=128, T=512, I=2, H=1024, NM=8, MS=128.
// Round 2: fma.rn.f32x2 packed math in chains + GEMMs, 128x64-tile
// double-buffered GEMM, 1-sync pipelined chain step with fast tanh.

#define NB   128
#define NT   512
#define NH   1024
#define NMOD 8
#define MSZ  128

__constant__ int c_TOFF[8] = {0, 513, 770, 899, 964, 997, 1014, 1023};
__constant__ long long c_GOFF[8] = {0, 0, 4210688, 8437760, 11632640,
                                    13795328, 15187968, 16072704};

__device__ float g_traj[16842752];   // 1028 states * 128 b * 128
__device__ float g_G[16646144];      // per-module context GEMM outputs
__device__ float g_pout[1028 * NB * 2];

// packed f32x2 helpers ------------------------------------------------------
__device__ __forceinline__ void fma2(unsigned long long& d,
                                     unsigned long long a,
                                     unsigned long long b) {
    asm("fma.rn.f32x2 %0, %1, %2, %0;" : "+l"(d) : "l"(a), "l"(b));
}
union U4 { float4 f; unsigned long long u[2]; };
union U2 { unsigned long long u; float2 f; };

__device__ __forceinline__ float fast_tanh(float v) {
    float e = __expf(2.f * v);
    return 1.f - __fdividef(2.f, e + 1.f);
}

// ---------------------------------------------------------------------------
// h0 = x[:,0] @ enc_w.T  -> state 0 of every module trajectory
// ---------------------------------------------------------------------------
__global__ void h0_kernel(const float* __restrict__ x,
                          const float* __restrict__ enc_w) {
    const int b = blockIdx.x;
    const int m = blockIdx.y;
    const int r = threadIdx.x;
    const int h = m * MSZ + r;
    const float x0 = x[(size_t)b * (NT + 1) * 2 + 0];
    const float x1 = x[(size_t)b * (NT + 1) * 2 + 1];
    g_traj[((size_t)c_TOFF[m] * NB + b) * MSZ + r] =
        x0 * enc_w[h * 2 + 0] + x1 * enc_w[h * 2 + 1];
}

// ---------------------------------------------------------------------------
// Sequential diagonal chain for module M. One CTA per batch element.
// Thread r owns output unit r; 128 diag weights packed in 64 f32x2 regs.
// ---------------------------------------------------------------------------
template <int M>
__global__ __launch_bounds__(MSZ, 1) void chain_kernel(
    const float* __restrict__ x,
    const float* __restrict__ W_ih,
    const float* __restrict__ W_hh) {
    const int b = blockIdx.x;
    const int r = threadIdx.x;
    const int mbase = M * MSZ;
    __shared__ float h_s[2][MSZ];

    // weights: row (mbase+r), cols [mbase, mbase+128) packed as f32x2 pairs
    unsigned long long Wp[MSZ / 2];
#pragma unroll
    for (int c4 = 0; c4 < MSZ / 4; c4++) {
        U4 w;
        w.f = *(const float4*)(W_hh + (size_t)(mbase + r) * NH + mbase +
                               c4 * 4);
        Wp[2 * c4 + 0] = w.u[0];
        Wp[2 * c4 + 1] = w.u[1];
    }
    const float wih0 = W_ih[(mbase + r) * 2 + 0];
    const float wih1 = W_ih[(mbase + r) * 2 + 1];

    const size_t tbase = ((size_t)c_TOFF[M] * NB + b) * MSZ;
    h_s[0][r] = g_traj[tbase + r];
    __syncthreads();

    const int K = NT >> M;

    // prefetch external context for step 0 (t=0 -> state index 0)
    float xn0 = x[((size_t)b * (NT + 1) + 1) * 2 + 0];
    float xn1 = x[((size_t)b * (NT + 1) + 1) * 2 + 1];
    float gg[8];
#pragma unroll
    for (int mp = M + 1; mp < NMOD; mp++)
        gg[mp - M - 1] =
            g_G[c_GOFF[mp] + (size_t)b * (mp * MSZ) + mbase + r];

    int p = 0;
    for (int k = 0; k < K; k++) {
        float gsum = xn0 * wih0 + xn1 * wih1;
#pragma unroll
        for (int mp = M + 1; mp < NMOD; mp++) gsum += gg[mp - M - 1];

        // issue next step's gathers early (hidden behind this step's math)
        float xt0 = 0.f, xt1 = 0.f, gt[8];
        if (k + 1 < K) {
            const int t2 = (k + 1) << M;
            xt0 = x[((size_t)b * (NT + 1) + (t2 + 1)) * 2 + 0];
            xt1 = x[((size_t)b * (NT + 1) + (t2 + 1)) * 2 + 1];
#pragma unroll
            for (int mp = M + 1; mp < NMOD; mp++) {
                const int s = ((t2 - 1) >> mp) + 1;
                gt[mp - M - 1] = g_G[c_GOFF[mp] +
                                     (size_t)(s * NB + b) * (mp * MSZ) +
                                     mbase + r];
            }
        }

        // packed diag matvec: 64 FFMA2 over 4 independent accumulators
        unsigned long long acc[4] = {0, 0, 0, 0};
        const float4* h4 = (const float4*)h_s[p];
#pragma unroll
        for (int c4 = 0; c4 < MSZ / 4; c4++) {
            U4 hv;
            hv.f = h4[c4];
            fma2(acc[(2 * c4) & 3], Wp[2 * c4], hv.u[0]);
            fma2(acc[(2 * c4 + 1) & 3], Wp[2 * c4 + 1], hv.u[1]);
        }
        float tot = gsum;
#pragma unroll
        for (int i = 0; i < 4; i++) {
            U2 a;
            a.u = acc[i];
            tot += a.f.x + a.f.y;
        }
        const float hn = fast_tanh(tot);

        h_s[p ^ 1][r] = hn;
        g_traj[tbase + (size_t)(k + 1) * (NB * MSZ) + r] = hn;
        __syncthreads();
        p ^= 1;

        xn0 = xt0; xn1 = xt1;
#pragma unroll
        for (int mp = M + 1; mp < NMOD; mp++) gg[mp - M - 1] = gt[mp - M - 1];
    }
}

// ---------------------------------------------------------------------------
// G_{mp} = Traj_{mp} (S_mp*128 x 128) @ W_hh[0:mp*128, mp-block]^T
// 128x64 tile, K=128 in 8 double-buffered chunks of 16, packed-K f32x2.
// smem is m-major so K-pairs come straight out of LDS.128.
// ---------------------------------------------------------------------------
__global__ __launch_bounds__(256, 2) void g_kernel(const float* __restrict__ W_hh,
                                                   int mp) {
    __shared__ float As[2][128][20];
    __shared__ float Bs[2][64][20];
    const int N = mp * MSZ;
    const float* A = g_traj + (size_t)c_TOFF[mp] * (NB * MSZ);
    float* C = g_G + c_GOFF[mp];
    const int row0 = blockIdx.x * 128;
    const int n0 = blockIdx.y * 64;
    const int tid = threadIdx.x;
    const int tx = tid & 15;   // 16 col-groups of 4
    const int ty = tid >> 4;   // 16 row-groups of 8

    // A-load role: 2 float4 per thread; B-load role: 1 float4
    const int arow0 = tid >> 2, ac4 = tid & 3;          // + second at tid+256
    const int arow1 = (tid + 256) >> 2;
    const int brow = tid >> 2, bc4 = tid & 3;

    const float* Ap0 = A + (size_t)(row0 + arow0) * MSZ + ac4 * 4;
    const float* Ap1 = A + (size_t)(row0 + arow1) * MSZ + ac4 * 4;
    const float* Bp  = W_hh + (size_t)(n0 + brow) * NH + mp * MSZ + bc4 * 4;

    float4 pa0 = *(const float4*)(Ap0);
    float4 pa1 = *(const float4*)(Ap1);
    float4 pb  = *(const float4*)(Bp);
    *(float4*)&As[0][arow0][ac4 * 4] = pa0;
    *(float4*)&As[0][arow1][ac4 * 4] = pa1;
    *(float4*)&Bs[0][brow][bc4 * 4] = pb;
    __syncthreads();

    unsigned long long acc[8][4];
#pragma unroll
    for (int i = 0; i < 8; i++)
#pragma unroll
        for (int j = 0; j < 4; j++) acc[i][j] = 0ull;

#pragma unroll
    for (int c = 0; c < 8; c++) {
        const int buf = c & 1;
        if (c < 7) {
            pa0 = *(const float4*)(Ap0 + (c + 1) * 16);
            pa1 = *(const float4*)(Ap1 + (c + 1) * 16);
            pb  = *(const float4*)(Bp + (c + 1) * 16);
        }
#pragma unroll
        for (int k4 = 0; k4 < 4; k4++) {
            U4 bfrag[4];
#pragma unroll
            for (int j = 0; j < 4; j++)
                bfrag[j].f = *(const float4*)&Bs[buf][tx * 4 + j][k4 * 4];
#pragma unroll
            for (int half = 0; half < 2; half++) {
                U4 afrag[4];
#pragma unroll
                for (int i2 = 0; i2 < 4; i2++)
                    afrag[i2].f = *(const float4*)
                        &As[buf][ty * 8 + half * 4 + i2][k4 * 4];
#pragma unroll
                for (int i2 = 0; i2 < 4; i2++)
#pragma unroll
                    for (int j = 0; j < 4; j++) {
                        fma2(acc[half * 4 + i2][j], afrag[i2].u[0],
                             bfrag[j].u[0]);
                        fma2(acc[half * 4 + i2][j], afrag[i2].u[1],
                             bfrag[j].u[1]);
                    }
            }
        }
        if (c < 7) {
            const int nb = (c + 1) & 1;
            *(float4*)&As[nb][arow0][ac4 * 4] = pa0;
            *(float4*)&As[nb][arow1][ac4 * 4] = pa1;
            *(float4*)&Bs[nb][brow][bc4 * 4] = pb;
            __syncthreads();
        }
    }

#pragma unroll
    for (int i = 0; i < 8; i++) {
        float4 out;
        U2 a0, a1, a2, a3;
        a0.u = acc[i][0]; a1.u = acc[i][1];
        a2.u = acc[i][2]; a3.u = acc[i][3];
        out.x = a0.f.x + a0.f.y;
        out.y = a1.f.x + a1.f.y;
        out.z = a2.f.x + a2.f.y;
        out.w = a3.f.x + a3.f.y;
        *(float4*)&C[(size_t)(row0 + ty * 8 + i) * N + n0 + tx * 4] = out;
    }
}

// ---------------------------------------------------------------------------
// fc partials per stored state: pout[gs,b,i] = Traj[gs,b,:] . fc_w[i, m-block]
// ---------------------------------------------------------------------------
__global__ __launch_bounds__(MSZ) void pout_kernel(
    const float* __restrict__ fc_w) {
    const int gs = blockIdx.x;
    const int b = blockIdx.y;
    const int r = threadIdx.x;
    int m = 0;
#pragma unroll
    for (int j = 1; j < 8; j++)
        if (gs >= c_TOFF[j]) m = j;
    const float v = g_traj[((size_t)gs * NB + b) * MSZ + r];
    const int col = m * MSZ + r;
    float a0 = v * fc_w[col];
    float a1 = v * fc_w[NH + col];
#pragma unroll
    for (int off = 16; off > 0; off >>= 1) {
        a0 += __shfl_down_sync(0xffffffffu, a0, off);
        a1 += __shfl_down_sync(0xffffffffu, a1, off);
    }
    __shared__ float s0[4], s1[4];
    if ((r & 31) == 0) { s0[r >> 5] = a0; s1[r >> 5] = a1; }
    __syncthreads();
    if (r == 0) {
        g_pout[((size_t)gs * NB + b) * 2 + 0] = s0[0] + s0[1] + s0[2] + s0[3];
        g_pout[((size_t)gs * NB + b) * 2 + 1] = s1[0] + s1[1] + s1[2] + s1[3];
    }
}

// ---------------------------------------------------------------------------
// out[b,t,i] = fc_b[i] + sum_m pout[state_of(m,t), b, i]
// ---------------------------------------------------------------------------
__global__ void assemble_kernel(const float* __restrict__ fc_b,
                                float* __restrict__ out) {
    const int idx = blockIdx.x * blockDim.x + threadIdx.x;  // b*512 + t
    const int b = idx >> 9;
    const int t = idx & 511;
    float o0 = fc_b[0];
    float o1 = fc_b[1];
#pragma unroll
    for (int m = 0; m < NMOD; m++) {
        const int gs = c_TOFF[m] + (t >> m) + 1;
        o0 += g_pout[((size_t)gs * NB + b) * 2 + 0];
        o1 += g_pout[((size_t)gs * NB + b) * 2 + 1];
    }
    out[(size_t)idx * 2 + 0] = o0;
    out[(size_t)idx * 2 + 1] = o1;
}

// ---------------------------------------------------------------------------
extern "C" void kernel_launch(void* const* d_in, const int* in_sizes, int n_in,
                              void* d_out, int out_size) {
    const float* x     = (const float*)d_in[0];
    const float* W_ih  = (const float*)d_in[1];
    const float* W_hh  = (const float*)d_in[2];
    const float* fc_w  = (const float*)d_in[3];
    const float* fc_b  = (const float*)d_in[4];
    const float* enc_w = (const float*)d_in[5];
    float* out = (float*)d_out;

    h0_kernel<<<dim3(NB, 8), MSZ>>>(x, enc_w);

    // S_mp = {_,257,129,65,33,17,9,5}; grid = (S_mp, 2*mp) for 128x64 tiles
    chain_kernel<7><<<NB, MSZ>>>(x, W_ih, W_hh);
    g_kernel<<<dim3(5, 14), 256>>>(W_hh, 7);
    chain_kernel<6><<<NB, MSZ>>>(x, W_ih, W_hh);
    g_kernel<<<dim3(9, 12), 256>>>(W_hh, 6);
    chain_kernel<5><<<NB, MSZ>>>(x, W_ih, W_hh);
    g_kernel<<<dim3(17, 10), 256>>>(W_hh, 5);
    chain_kernel<4><<<NB, MSZ>>>(x, W_ih, W_hh);
    g_kernel<<<dim3(33, 8), 256>>>(W_hh, 4);
    chain_kernel<3><<<NB, MSZ>>>(x, W_ih, W_hh);
    g_kernel<<<dim3(65, 6), 256>>>(W_hh, 3);
    chain_kernel<2><<<NB, MSZ>>>(x, W_ih, W_hh);
    g_kernel<<<dim3(129, 4), 256>>>(W_hh, 2);
    chain_kernel<1><<<NB, MSZ>>>(x, W_ih, W_hh);
    g_kernel<<<dim3(257, 2), 256>>>(W_hh, 1);
    chain_kernel<0><<<NB, MSZ>>>(x, W_ih, W_hh);

    pout_kernel<<<dim3(1028, NB), MSZ>>>(fc_w);
    assemble_kernel<<<(NB * NT) / 256, 256>>>(fc_b, out);
}

// round 3
// speedup vs baseline: 1.2018x; 1.0350x over previous
#include <cuda_runtime.h>
#include <math.h>

// Clockwork RNN, hierarchically decomposed.
// B=128, T=512, I=2, H=1024, NM=8, MS=128.
// Round 3: un-spill g_kernel (launch_bounds fix), block-per-state pout,
// inline h0 into chains, 8-acc packed chains.

#define NB   128
#define NT   512
#define NH   1024
#define NMOD 8
#define MSZ  128

__constant__ int c_TOFF[8] = {0, 513, 770, 899, 964, 997, 1014, 1023};
__constant__ long long c_GOFF[8] = {0, 0, 4210688, 8437760, 11632640,
                                    13795328, 15187968, 16072704};

__device__ float g_traj[16842752];   // 1028 states * 128 b * 128
__device__ float g_G[16646144];      // per-module context GEMM outputs
__device__ float g_pout[1028 * NB * 2];

// packed f32x2 helpers ------------------------------------------------------
__device__ __forceinline__ void fma2(unsigned long long& d,
                                     unsigned long long a,
                                     unsigned long long b) {
    asm("fma.rn.f32x2 %0, %1, %2, %0;" : "+l"(d) : "l"(a), "l"(b));
}
__device__ __forceinline__ unsigned long long add2(unsigned long long a,
                                                   unsigned long long b) {
    unsigned long long d;
    asm("add.rn.f32x2 %0, %1, %2;" : "=l"(d) : "l"(a), "l"(b));
    return d;
}
union U4 { float4 f; unsigned long long u[2]; };
union U2 { unsigned long long u; float2 f; };

__device__ __forceinline__ float fast_tanh(float v) {
    float e = __expf(2.f * v);
    return 1.f - __fdividef(2.f, e + 1.f);
}

// ---------------------------------------------------------------------------
// Sequential diagonal chain for module M. One CTA per batch element.
// Thread r owns output unit r; 128 diag weights packed in 64 f32x2 regs.
// h0 (encoder) computed inline; trajectory stored for later GEMM/pout.
// ---------------------------------------------------------------------------
template <int M>
__global__ __launch_bounds__(MSZ, 1) void chain_kernel(
    const float* __restrict__ x,
    const float* __restrict__ W_ih,
    const float* __restrict__ W_hh,
    const float* __restrict__ enc_w) {
    const int b = blockIdx.x;
    const int r = threadIdx.x;
    const int mbase = M * MSZ;
    __shared__ float h_s[2][MSZ];

    unsigned long long Wp[MSZ / 2];
#pragma unroll
    for (int c4 = 0; c4 < MSZ / 4; c4++) {
        U4 w;
        w.f = *(const float4*)(W_hh + (size_t)(mbase + r) * NH + mbase +
                               c4 * 4);
        Wp[2 * c4 + 0] = w.u[0];
        Wp[2 * c4 + 1] = w.u[1];
    }
    const float wih0 = W_ih[(mbase + r) * 2 + 0];
    const float wih1 = W_ih[(mbase + r) * 2 + 1];

    // h0 = x[:,0] @ enc_w.T (module M rows)
    const float x00 = x[(size_t)b * (NT + 1) * 2 + 0];
    const float x01 = x[(size_t)b * (NT + 1) * 2 + 1];
    const float h0v = x00 * enc_w[(mbase + r) * 2 + 0] +
                      x01 * enc_w[(mbase + r) * 2 + 1];
    const size_t tbase = ((size_t)c_TOFF[M] * NB + b) * MSZ;
    h_s[0][r] = h0v;
    g_traj[tbase + r] = h0v;
    __syncthreads();

    const int K = NT >> M;

    // prefetch external context for step 0 (t=0 -> state index 0)
    float xn0 = x[((size_t)b * (NT + 1) + 1) * 2 + 0];
    float xn1 = x[((size_t)b * (NT + 1) + 1) * 2 + 1];
    float gg[8];
#pragma unroll
    for (int mp = M + 1; mp < NMOD; mp++)
        gg[mp - M - 1] =
            g_G[c_GOFF[mp] + (size_t)b * (mp * MSZ) + mbase + r];

    int p = 0;
    for (int k = 0; k < K; k++) {
        float gsum = xn0 * wih0 + xn1 * wih1;
#pragma unroll
        for (int mp = M + 1; mp < NMOD; mp++) gsum += gg[mp - M - 1];

        // issue next step's gathers early (hidden behind this step's math)
        float xt0 = 0.f, xt1 = 0.f, gt[8];
        if (k + 1 < K) {
            const int t2 = (k + 1) << M;
            xt0 = x[((size_t)b * (NT + 1) + (t2 + 1)) * 2 + 0];
            xt1 = x[((size_t)b * (NT + 1) + (t2 + 1)) * 2 + 1];
#pragma unroll
            for (int mp = M + 1; mp < NMOD; mp++) {
                const int s = ((t2 - 1) >> mp) + 1;
                gt[mp - M - 1] = g_G[c_GOFF[mp] +
                                     (size_t)(s * NB + b) * (mp * MSZ) +
                                     mbase + r];
            }
        }

        // packed diag matvec: 64 FFMA2 over 8 independent accumulators
        unsigned long long acc[8] = {0, 0, 0, 0, 0, 0, 0, 0};
        const float4* h4 = (const float4*)h_s[p];
#pragma unroll
        for (int c4 = 0; c4 < MSZ / 4; c4++) {
            U4 hv;
            hv.f = h4[c4];
            fma2(acc[(2 * c4) & 7], Wp[2 * c4], hv.u[0]);
            fma2(acc[(2 * c4 + 1) & 7], Wp[2 * c4 + 1], hv.u[1]);
        }
        // packed tree reduce
        acc[0] = add2(acc[0], acc[1]);
        acc[2] = add2(acc[2], acc[3]);
        acc[4] = add2(acc[4], acc[5]);
        acc[6] = add2(acc[6], acc[7]);
        acc[0] = add2(acc[0], acc[2]);
        acc[4] = add2(acc[4], acc[6]);
        acc[0] = add2(acc[0], acc[4]);
        U2 a;
        a.u = acc[0];
        const float hn = fast_tanh(a.f.x + a.f.y + gsum);

        h_s[p ^ 1][r] = hn;
        g_traj[tbase + (size_t)(k + 1) * (NB * MSZ) + r] = hn;
        __syncthreads();
        p ^= 1;

        xn0 = xt0; xn1 = xt1;
#pragma unroll
        for (int mp = M + 1; mp < NMOD; mp++) gg[mp - M - 1] = gt[mp - M - 1];
    }
}

// ---------------------------------------------------------------------------
// G_{mp} = Traj_{mp} (S_mp*128 x 128) @ W_hh[0:mp*128, mp-block]^T
// 128x64 tile, K=128 in 8 double-buffered chunks of 16, packed-K f32x2.
// NOTE: no min-blocks clause — the accumulator file needs ~140 regs and a
// 128-reg cap (2 CTAs/SM) forces local-memory spills in the inner loop.
// ---------------------------------------------------------------------------
__global__ __launch_bounds__(256) void g_kernel(const float* __restrict__ W_hh,
                                                int mp) {
    __shared__ float As[2][128][20];
    __shared__ float Bs[2][64][20];
    const int N = mp * MSZ;
    const float* A = g_traj + (size_t)c_TOFF[mp] * (NB * MSZ);
    float* C = g_G + c_GOFF[mp];
    const int row0 = blockIdx.x * 128;
    const int n0 = blockIdx.y * 64;
    const int tid = threadIdx.x;
    const int tx = tid & 15;   // 16 col-groups of 4
    const int ty = tid >> 4;   // 16 row-groups of 8

    const int arow0 = tid >> 2, ac4 = tid & 3;
    const int arow1 = (tid + 256) >> 2;
    const int brow = tid >> 2, bc4 = tid & 3;

    const float* Ap0 = A + (size_t)(row0 + arow0) * MSZ + ac4 * 4;
    const float* Ap1 = A + (size_t)(row0 + arow1) * MSZ + ac4 * 4;
    const float* Bp  = W_hh + (size_t)(n0 + brow) * NH + mp * MSZ + bc4 * 4;

    float4 pa0 = *(const float4*)(Ap0);
    float4 pa1 = *(const float4*)(Ap1);
    float4 pb  = *(const float4*)(Bp);
    *(float4*)&As[0][arow0][ac4 * 4] = pa0;
    *(float4*)&As[0][arow1][ac4 * 4] = pa1;
    *(float4*)&Bs[0][brow][bc4 * 4] = pb;
    __syncthreads();

    unsigned long long acc[8][4];
#pragma unroll
    for (int i = 0; i < 8; i++)
#pragma unroll
        for (int j = 0; j < 4; j++) acc[i][j] = 0ull;

#pragma unroll
    for (int c = 0; c < 8; c++) {
        const int buf = c & 1;
        if (c < 7) {
            pa0 = *(const float4*)(Ap0 + (c + 1) * 16);
            pa1 = *(const float4*)(Ap1 + (c + 1) * 16);
            pb  = *(const float4*)(Bp + (c + 1) * 16);
        }
#pragma unroll
        for (int k4 = 0; k4 < 4; k4++) {
            U4 bfrag[4];
#pragma unroll
            for (int j = 0; j < 4; j++)
                bfrag[j].f = *(const float4*)&Bs[buf][tx * 4 + j][k4 * 4];
#pragma unroll
            for (int half = 0; half < 2; half++) {
                U4 afrag[4];
#pragma unroll
                for (int i2 = 0; i2 < 4; i2++)
                    afrag[i2].f = *(const float4*)
                        &As[buf][ty * 8 + half * 4 + i2][k4 * 4];
#pragma unroll
                for (int i2 = 0; i2 < 4; i2++)
#pragma unroll
                    for (int j = 0; j < 4; j++) {
                        fma2(acc[half * 4 + i2][j], afrag[i2].u[0],
                             bfrag[j].u[0]);
                        fma2(acc[half * 4 + i2][j], afrag[i2].u[1],
                             bfrag[j].u[1]);
                    }
            }
        }
        if (c < 7) {
            const int nb = (c + 1) & 1;
            *(float4*)&As[nb][arow0][ac4 * 4] = pa0;
            *(float4*)&As[nb][arow1][ac4 * 4] = pa1;
            *(float4*)&Bs[nb][brow][bc4 * 4] = pb;
            __syncthreads();
        }
    }

#pragma unroll
    for (int i = 0; i < 8; i++) {
        float4 out;
        U2 a0, a1, a2, a3;
        a0.u = acc[i][0]; a1.u = acc[i][1];
        a2.u = acc[i][2]; a3.u = acc[i][3];
        out.x = a0.f.x + a0.f.y;
        out.y = a1.f.x + a1.f.y;
        out.z = a2.f.x + a2.f.y;
        out.w = a3.f.x + a3.f.y;
        *(float4*)&C[(size_t)(row0 + ty * 8 + i) * N + n0 + tx * 4] = out;
    }
}

// ---------------------------------------------------------------------------
// fc partials: one CTA per stored state; 8 warps sweep the 128 batch rows.
// pout[gs,b,i] = Traj[gs,b,:] . fc_w[i, m-block]
// ---------------------------------------------------------------------------
__global__ __launch_bounds__(256) void pout_kernel(
    const float* __restrict__ fc_w) {
    const int gs = blockIdx.x;
    const int warp = threadIdx.x >> 5;
    const int lane = threadIdx.x & 31;
    int m = 0;
#pragma unroll
    for (int j = 1; j < 8; j++)
        if (gs >= c_TOFF[j]) m = j;
    const int col = m * MSZ + lane * 4;
    const float4 w0 = *(const float4*)(fc_w + col);
    const float4 w1 = *(const float4*)(fc_w + NH + col);
    const float* base = g_traj + (size_t)gs * (NB * MSZ);

    for (int b = warp; b < NB; b += 8) {
        const float4 v = *(const float4*)(base + (size_t)b * MSZ + lane * 4);
        float a0 = v.x * w0.x + v.y * w0.y + v.z * w0.z + v.w * w0.w;
        float a1 = v.x * w1.x + v.y * w1.y + v.z * w1.z + v.w * w1.w;
#pragma unroll
        for (int off = 16; off > 0; off >>= 1) {
            a0 += __shfl_xor_sync(0xffffffffu, a0, off);
            a1 += __shfl_xor_sync(0xffffffffu, a1, off);
        }
        if (lane == 0) {
            g_pout[((size_t)gs * NB + b) * 2 + 0] = a0;
            g_pout[((size_t)gs * NB + b) * 2 + 1] = a1;
        }
    }
}

// ---------------------------------------------------------------------------
// out[b,t,i] = fc_b[i] + sum_m pout[state_of(m,t), b, i]
// ---------------------------------------------------------------------------
__global__ void assemble_kernel(const float* __restrict__ fc_b,
                                float* __restrict__ out) {
    const int idx = blockIdx.x * blockDim.x + threadIdx.x;  // b*512 + t
    const int b = idx >> 9;
    const int t = idx & 511;
    float o0 = fc_b[0];
    float o1 = fc_b[1];
#pragma unroll
    for (int m = 0; m < NMOD; m++) {
        const int gs = c_TOFF[m] + (t >> m) + 1;
        o0 += g_pout[((size_t)gs * NB + b) * 2 + 0];
        o1 += g_pout[((size_t)gs * NB + b) * 2 + 1];
    }
    out[(size_t)idx * 2 + 0] = o0;
    out[(size_t)idx * 2 + 1] = o1;
}

// ---------------------------------------------------------------------------
extern "C" void kernel_launch(void* const* d_in, const int* in_sizes, int n_in,
                              void* d_out, int out_size) {
    const float* x     = (const float*)d_in[0];
    const float* W_ih  = (const float*)d_in[1];
    const float* W_hh  = (const float*)d_in[2];
    const float* fc_w  = (const float*)d_in[3];
    const float* fc_b  = (const float*)d_in[4];
    const float* enc_w = (const float*)d_in[5];
    float* out = (float*)d_out;

    // S_mp = {_,257,129,65,33,17,9,5}; grid = (ceil(S*128/128), 2*mp)
    chain_kernel<7><<<NB, MSZ>>>(x, W_ih, W_hh, enc_w);
    g_kernel<<<dim3(5, 14), 256>>>(W_hh, 7);
    chain_kernel<6><<<NB, MSZ>>>(x, W_ih, W_hh, enc_w);
    g_kernel<<<dim3(9, 12), 256>>>(W_hh, 6);
    chain_kernel<5><<<NB, MSZ>>>(x, W_ih, W_hh, enc_w);
    g_kernel<<<dim3(17, 10), 256>>>(W_hh, 5);
    chain_kernel<4><<<NB, MSZ>>>(x, W_ih, W_hh, enc_w);
    g_kernel<<<dim3(33, 8), 256>>>(W_hh, 4);
    chain_kernel<3><<<NB, MSZ>>>(x, W_ih, W_hh, enc_w);
    g_kernel<<<dim3(65, 6), 256>>>(W_hh, 3);
    chain_kernel<2><<<NB, MSZ>>>(x, W_ih, W_hh, enc_w);
    g_kernel<<<dim3(129, 4), 256>>>(W_hh, 2);
    chain_kernel<1><<<NB, MSZ>>>(x, W_ih, W_hh, enc_w);
    g_kernel<<<dim3(257, 2), 256>>>(W_hh, 1);
    chain_kernel<0><<<NB, MSZ>>>(x, W_ih, W_hh, enc_w);

    pout_kernel<<<1028, 256>>>(fc_w);
    assemble_kernel<<<(NB * NT) / 256, 256>>>(fc_b, out);
}

// round 4
// speedup vs baseline: 1.3559x; 1.1283x over previous
#include <cuda_runtime.h>
#include <math.h>

// Clockwork RNN, hierarchically decomposed.
// B=128, T=512, I=2, H=1024, NM=8, MS=128.
// Round 4: g_kernel rebuilt -> 64x64 tile, 256 thr, 2 CTAs/SM guaranteed,
// conflict-free B-fragment smem mapping. Chains unchanged.

#define NB   128
#define NT   512
#define NH   1024
#define NMOD 8
#define MSZ  128

__constant__ int c_TOFF[8] = {0, 513, 770, 899, 964, 997, 1014, 1023};
__constant__ long long c_GOFF[8] = {0, 0, 4210688, 8437760, 11632640,
                                    13795328, 15187968, 16072704};

__device__ float g_traj[16842752];   // 1028 states * 128 b * 128
__device__ float g_G[16646144];      // per-module context GEMM outputs
__device__ float g_pout[1028 * NB * 2];

// packed f32x2 helpers ------------------------------------------------------
__device__ __forceinline__ void fma2(unsigned long long& d,
                                     unsigned long long a,
                                     unsigned long long b) {
    asm("fma.rn.f32x2 %0, %1, %2, %0;" : "+l"(d) : "l"(a), "l"(b));
}
__device__ __forceinline__ unsigned long long add2(unsigned long long a,
                                                   unsigned long long b) {
    unsigned long long d;
    asm("add.rn.f32x2 %0, %1, %2;" : "=l"(d) : "l"(a), "l"(b));
    return d;
}
union U4 { float4 f; unsigned long long u[2]; };
union U2 { unsigned long long u; float2 f; };

__device__ __forceinline__ float fast_tanh(float v) {
    float e = __expf(2.f * v);
    return 1.f - __fdividef(2.f, e + 1.f);
}

// ---------------------------------------------------------------------------
// Sequential diagonal chain for module M. One CTA per batch element.
// Thread r owns output unit r; 128 diag weights packed in 64 f32x2 regs.
// ---------------------------------------------------------------------------
template <int M>
__global__ __launch_bounds__(MSZ, 1) void chain_kernel(
    const float* __restrict__ x,
    const float* __restrict__ W_ih,
    const float* __restrict__ W_hh,
    const float* __restrict__ enc_w) {
    const int b = blockIdx.x;
    const int r = threadIdx.x;
    const int mbase = M * MSZ;
    __shared__ float h_s[2][MSZ];

    unsigned long long Wp[MSZ / 2];
#pragma unroll
    for (int c4 = 0; c4 < MSZ / 4; c4++) {
        U4 w;
        w.f = *(const float4*)(W_hh + (size_t)(mbase + r) * NH + mbase +
                               c4 * 4);
        Wp[2 * c4 + 0] = w.u[0];
        Wp[2 * c4 + 1] = w.u[1];
    }
    const float wih0 = W_ih[(mbase + r) * 2 + 0];
    const float wih1 = W_ih[(mbase + r) * 2 + 1];

    // h0 = x[:,0] @ enc_w.T (module M rows)
    const float x00 = x[(size_t)b * (NT + 1) * 2 + 0];
    const float x01 = x[(size_t)b * (NT + 1) * 2 + 1];
    const float h0v = x00 * enc_w[(mbase + r) * 2 + 0] +
                      x01 * enc_w[(mbase + r) * 2 + 1];
    const size_t tbase = ((size_t)c_TOFF[M] * NB + b) * MSZ;
    h_s[0][r] = h0v;
    g_traj[tbase + r] = h0v;
    __syncthreads();

    const int K = NT >> M;

    float xn0 = x[((size_t)b * (NT + 1) + 1) * 2 + 0];
    float xn1 = x[((size_t)b * (NT + 1) + 1) * 2 + 1];
    float gg[8];
#pragma unroll
    for (int mp = M + 1; mp < NMOD; mp++)
        gg[mp - M - 1] =
            g_G[c_GOFF[mp] + (size_t)b * (mp * MSZ) + mbase + r];

    int p = 0;
    for (int k = 0; k < K; k++) {
        float gsum = xn0 * wih0 + xn1 * wih1;
#pragma unroll
        for (int mp = M + 1; mp < NMOD; mp++) gsum += gg[mp - M - 1];

        float xt0 = 0.f, xt1 = 0.f, gt[8];
        if (k + 1 < K) {
            const int t2 = (k + 1) << M;
            xt0 = x[((size_t)b * (NT + 1) + (t2 + 1)) * 2 + 0];
            xt1 = x[((size_t)b * (NT + 1) + (t2 + 1)) * 2 + 1];
#pragma unroll
            for (int mp = M + 1; mp < NMOD; mp++) {
                const int s = ((t2 - 1) >> mp) + 1;
                gt[mp - M - 1] = g_G[c_GOFF[mp] +
                                     (size_t)(s * NB + b) * (mp * MSZ) +
                                     mbase + r];
            }
        }

        unsigned long long acc[8] = {0, 0, 0, 0, 0, 0, 0, 0};
        const float4* h4 = (const float4*)h_s[p];
#pragma unroll
        for (int c4 = 0; c4 < MSZ / 4; c4++) {
            U4 hv;
            hv.f = h4[c4];
            fma2(acc[(2 * c4) & 7], Wp[2 * c4], hv.u[0]);
            fma2(acc[(2 * c4 + 1) & 7], Wp[2 * c4 + 1], hv.u[1]);
        }
        acc[0] = add2(acc[0], acc[1]);
        acc[2] = add2(acc[2], acc[3]);
        acc[4] = add2(acc[4], acc[5]);
        acc[6] = add2(acc[6], acc[7]);
        acc[0] = add2(acc[0], acc[2]);
        acc[4] = add2(acc[4], acc[6]);
        acc[0] = add2(acc[0], acc[4]);
        U2 a;
        a.u = acc[0];
        const float hn = fast_tanh(a.f.x + a.f.y + gsum);

        h_s[p ^ 1][r] = hn;
        g_traj[tbase + (size_t)(k + 1) * (NB * MSZ) + r] = hn;
        __syncthreads();
        p ^= 1;

        xn0 = xt0; xn1 = xt1;
#pragma unroll
        for (int mp = M + 1; mp < NMOD; mp++) gg[mp - M - 1] = gt[mp - M - 1];
    }
}

// ---------------------------------------------------------------------------
// G_{mp} = Traj_{mp} (S_mp*128 x 128) @ W_hh[0:mp*128, mp-block]^T
// 64x64 tile, 256 threads, 4x4 per-thread packed-K f32x2 micro-tile.
// __launch_bounds__(256,2): <=128 regs -> exactly 2 CTAs/SM (64K regfile).
// B fragments: thread owns cols {tx, tx+16, tx+32, tx+48} -> smem read
// stride 20 floats -> <=2-way bank conflicts (the old 4tx..4tx+3 mapping
// was 8-way conflicted, capping the kernel at 13 TF/s).
// ---------------------------------------------------------------------------
__global__ __launch_bounds__(256, 2) void g_kernel(const float* __restrict__ W_hh,
                                                   int mp) {
    __shared__ float As[2][64][20];
    __shared__ float Bs[2][64][20];
    const int N = mp * MSZ;
    const float* A = g_traj + (size_t)c_TOFF[mp] * (NB * MSZ);
    float* C = g_G + c_GOFF[mp];
    const int row0 = blockIdx.x * 64;
    const int n0 = blockIdx.y * 64;
    const int tid = threadIdx.x;
    const int tx = tid & 15;   // 16 col lanes
    const int ty = tid >> 4;   // 16 row groups of 4

    const int lrow = tid >> 2, lc4 = tid & 3;

    const float* Ap = A + (size_t)(row0 + lrow) * MSZ + lc4 * 4;
    const float* Bp = W_hh + (size_t)(n0 + lrow) * NH + mp * MSZ + lc4 * 4;

    float4 pa = *(const float4*)Ap;
    float4 pb = *(const float4*)Bp;
    *(float4*)&As[0][lrow][lc4 * 4] = pa;
    *(float4*)&Bs[0][lrow][lc4 * 4] = pb;
    __syncthreads();

    unsigned long long acc[4][4];
#pragma unroll
    for (int i = 0; i < 4; i++)
#pragma unroll
        for (int j = 0; j < 4; j++) acc[i][j] = 0ull;

#pragma unroll
    for (int c = 0; c < 8; c++) {
        const int buf = c & 1;
        if (c < 7) {
            pa = *(const float4*)(Ap + (c + 1) * 16);
            pb = *(const float4*)(Bp + (c + 1) * 16);
        }
#pragma unroll
        for (int k4 = 0; k4 < 4; k4++) {
            U4 af[4], bf[4];
#pragma unroll
            for (int i = 0; i < 4; i++)
                af[i].f = *(const float4*)&As[buf][ty * 4 + i][k4 * 4];
#pragma unroll
            for (int j = 0; j < 4; j++)
                bf[j].f = *(const float4*)&Bs[buf][tx + j * 16][k4 * 4];
#pragma unroll
            for (int i = 0; i < 4; i++)
#pragma unroll
                for (int j = 0; j < 4; j++) {
                    fma2(acc[i][j], af[i].u[0], bf[j].u[0]);
                    fma2(acc[i][j], af[i].u[1], bf[j].u[1]);
                }
        }
        if (c < 7) {
            const int nb = buf ^ 1;
            *(float4*)&As[nb][lrow][lc4 * 4] = pa;
            *(float4*)&Bs[nb][lrow][lc4 * 4] = pb;
            __syncthreads();
        }
    }

#pragma unroll
    for (int i = 0; i < 4; i++)
#pragma unroll
        for (int j = 0; j < 4; j++) {
            U2 a;
            a.u = acc[i][j];
            C[(size_t)(row0 + ty * 4 + i) * N + n0 + tx + j * 16] =
                a.f.x + a.f.y;
        }
}

// ---------------------------------------------------------------------------
// fc partials: one CTA per stored state; 8 warps sweep the 128 batch rows.
// ---------------------------------------------------------------------------
__global__ __launch_bounds__(256) void pout_kernel(
    const float* __restrict__ fc_w) {
    const int gs = blockIdx.x;
    const int warp = threadIdx.x >> 5;
    const int lane = threadIdx.x & 31;
    int m = 0;
#pragma unroll
    for (int j = 1; j < 8; j++)
        if (gs >= c_TOFF[j]) m = j;
    const int col = m * MSZ + lane * 4;
    const float4 w0 = *(const float4*)(fc_w + col);
    const float4 w1 = *(const float4*)(fc_w + NH + col);
    const float* base = g_traj + (size_t)gs * (NB * MSZ);

    for (int b = warp; b < NB; b += 8) {
        const float4 v = *(const float4*)(base + (size_t)b * MSZ + lane * 4);
        float a0 = v.x * w0.x + v.y * w0.y + v.z * w0.z + v.w * w0.w;
        float a1 = v.x * w1.x + v.y * w1.y + v.z * w1.z + v.w * w1.w;
#pragma unroll
        for (int off = 16; off > 0; off >>= 1) {
            a0 += __shfl_xor_sync(0xffffffffu, a0, off);
            a1 += __shfl_xor_sync(0xffffffffu, a1, off);
        }
        if (lane == 0) {
            g_pout[((size_t)gs * NB + b) * 2 + 0] = a0;
            g_pout[((size_t)gs * NB + b) * 2 + 1] = a1;
        }
    }
}

// ---------------------------------------------------------------------------
// out[b,t,i] = fc_b[i] + sum_m pout[state_of(m,t), b, i]
// ---------------------------------------------------------------------------
__global__ void assemble_kernel(const float* __restrict__ fc_b,
                                float* __restrict__ out) {
    const int idx = blockIdx.x * blockDim.x + threadIdx.x;  // b*512 + t
    const int b = idx >> 9;
    const int t = idx & 511;
    float o0 = fc_b[0];
    float o1 = fc_b[1];
#pragma unroll
    for (int m = 0; m < NMOD; m++) {
        const int gs = c_TOFF[m] + (t >> m) + 1;
        o0 += g_pout[((size_t)gs * NB + b) * 2 + 0];
        o1 += g_pout[((size_t)gs * NB + b) * 2 + 1];
    }
    out[(size_t)idx * 2 + 0] = o0;
    out[(size_t)idx * 2 + 1] = o1;
}

// ---------------------------------------------------------------------------
extern "C" void kernel_launch(void* const* d_in, const int* in_sizes, int n_in,
                              void* d_out, int out_size) {
    const float* x     = (const float*)d_in[0];
    const float* W_ih  = (const float*)d_in[1];
    const float* W_hh  = (const float*)d_in[2];
    const float* fc_w  = (const float*)d_in[3];
    const float* fc_b  = (const float*)d_in[4];
    const float* enc_w = (const float*)d_in[5];
    float* out = (float*)d_out;

    // S_mp = {_,257,129,65,33,17,9,5}; grid = (2*S_mp, 2*mp) for 64x64 tiles
    chain_kernel<7><<<NB, MSZ>>>(x, W_ih, W_hh, enc_w);
    g_kernel<<<dim3(10, 14), 256>>>(W_hh, 7);
    chain_kernel<6><<<NB, MSZ>>>(x, W_ih, W_hh, enc_w);
    g_kernel<<<dim3(18, 12), 256>>>(W_hh, 6);
    chain_kernel<5><<<NB, MSZ>>>(x, W_ih, W_hh, enc_w);
    g_kernel<<<dim3(34, 10), 256>>>(W_hh, 5);
    chain_kernel<4><<<NB, MSZ>>>(x, W_ih, W_hh, enc_w);
    g_kernel<<<dim3(66, 8), 256>>>(W_hh, 4);
    chain_kernel<3><<<NB, MSZ>>>(x, W_ih, W_hh, enc_w);
    g_kernel<<<dim3(130, 6), 256>>>(W_hh, 3);
    chain_kernel<2><<<NB, MSZ>>>(x, W_ih, W_hh, enc_w);
    g_kernel<<<dim3(258, 4), 256>>>(W_hh, 2);
    chain_kernel<1><<<NB, MSZ>>>(x, W_ih, W_hh, enc_w);
    g_kernel<<<dim3(514, 2), 256>>>(W_hh, 1);
    chain_kernel<0><<<NB, MSZ>>>(x, W_ih, W_hh, enc_w);

    pout_kernel<<<1028, 256>>>(fc_w);
    assemble_kernel<<<(NB * NT) / 256, 256>>>(fc_b, out);
}